// round 9
// baseline (speedup 1.0000x reference)
#include <cuda_runtime.h>

// GCMConv: gauge-covariant convolution on 8x8x16x16 lattice.
// x: (1, 16384, 8, 3, 3, 2) float32  [channels: 4 gauge links U_a, 4 fields w_c]
// weight: (4, 9, 33) float32
// out: (1, 16384, 8, 3, 3, 2): [U (copied), w_out]
//
// M-form, scalar FFMA, 3-pass v-split (register-safe):
//   M_v = sum_k c1_{vk} T_k + c2_{vk} T_k^dag   (+ c3_v I at epilogue)
//   w_out[u] = M_8 + sum_c w_c @ M_c + w_c^dag @ M_{4+c}
// Passes: v in {0,1,2}, {3,4,5}, {6,7,8}. Live set per pass:
//   M 54 + T-ring 54 + acc 18 ~ 126 floats -> fits 168-reg cap, no spills.
// T streamed as 4x LDG.128 + 1x LDG.64 per matrix, ring-of-3 prefetch (depth 2).

#define NS 16384

// Scratch layout (element-pair-major for float4 loads):
//  g_T4[(r*4 + q)*NS + site] : elements 2q, 2q+1 of matrix r as (re,im,re,im)
//  g_T2[r*NS + site]         : element 8 of matrix r as (re,im)
//  r = 0..15 : T_k ; r = 16+c : own-site w_c
__device__ float4 g_T4[80 * NS];
__device__ float2 g_T2[20 * NS];

__global__ __launch_bounds__(256) void transport_kernel(const float* __restrict__ x) {
    int g = blockIdx.x * 256 + threadIdx.x;   // 0 .. 4*NS-1
    int site = g & (NS - 1);
    int a = g >> 14;                           // axis 0..3

    // periodic +1 neighbor; dims (8,8,16,16), strides (2048,256,16,1)
    int d3 = site & 15, d2 = (site >> 4) & 15, d1 = (site >> 8) & 7, d0 = (site >> 11) & 7;
    int nbr;
    if (a == 0)      nbr = site + ((((d0 + 1) & 7) - d0) << 11);
    else if (a == 1) nbr = site + ((((d1 + 1) & 7) - d1) << 8);
    else if (a == 2) nbr = site + ((((d2 + 1) & 15) - d2) << 4);
    else             nbr = site + (((d3 + 1) & 15) - d3);

    float Ur[3][3], Ui[3][3];
    {
        const float2* up = (const float2*)(x + site * 144 + a * 18);
#pragma unroll
        for (int m = 0; m < 9; m++) {
            float2 t = up[m];
            Ur[m / 3][m % 3] = t.x;
            Ui[m / 3][m % 3] = t.y;
        }
    }

#pragma unroll
    for (int c = 0; c < 4; c++) {
        float Wr[3][3], Wi[3][3];
        const float2* wp = (const float2*)(x + nbr * 144 + (4 + c) * 18);
#pragma unroll
        for (int m = 0; m < 9; m++) {
            float2 t = wp[m];
            Wr[m / 3][m % 3] = t.x;
            Wi[m / 3][m % 3] = t.y;
        }
        // t1 = U @ W
        float t1r[3][3], t1i[3][3];
#pragma unroll
        for (int i = 0; i < 3; i++)
#pragma unroll
            for (int kk = 0; kk < 3; kk++) {
                float cr = 0.f, ci = 0.f;
#pragma unroll
                for (int j = 0; j < 3; j++) {
                    cr += Ur[i][j] * Wr[j][kk] - Ui[i][j] * Wi[j][kk];
                    ci += Ur[i][j] * Wi[j][kk] + Ui[i][j] * Wr[j][kk];
                }
                t1r[i][kk] = cr;
                t1i[i][kk] = ci;
            }
        // T = t1 @ U^dag
        float Tr[9], Tiv[9];
#pragma unroll
        for (int i = 0; i < 3; i++)
#pragma unroll
            for (int kk = 0; kk < 3; kk++) {
                float cr = 0.f, ci = 0.f;
#pragma unroll
                for (int j = 0; j < 3; j++) {
                    float br = Ur[kk][j], bi = -Ui[kk][j];
                    cr += t1r[i][j] * br - t1i[i][j] * bi;
                    ci += t1r[i][j] * bi + t1i[i][j] * br;
                }
                Tr[i * 3 + kk] = cr;
                Tiv[i * 3 + kk] = ci;
            }
        int r = a * 4 + c;
#pragma unroll
        for (int q = 0; q < 4; q++)
            g_T4[(r * 4 + q) * NS + site] =
                make_float4(Tr[2 * q], Tiv[2 * q], Tr[2 * q + 1], Tiv[2 * q + 1]);
        g_T2[r * NS + site] = make_float2(Tr[8], Tiv[8]);
    }

    // own-site field: thread (site, a) handles channel c = a
    {
        const float2* wp = (const float2*)(x + site * 144 + (4 + a) * 18);
        float2 e[9];
#pragma unroll
        for (int m = 0; m < 9; m++) e[m] = wp[m];
        int r = 16 + a;
#pragma unroll
        for (int q = 0; q < 4; q++)
            g_T4[(r * 4 + q) * NS + site] =
                make_float4(e[2 * q].x, e[2 * q].y, e[2 * q + 1].x, e[2 * q + 1].y);
        g_T2[r * NS + site] = e[8];
    }
}

__global__ __launch_bounds__(128, 3) void contract_kernel(const float* __restrict__ x,
                                                          const float* __restrict__ weight,
                                                          float* __restrict__ out) {
    __shared__ float wt[297];   // [w*9 + v] = weight[u, v, w]

    int g = blockIdx.x * 128 + threadIdx.x;
    int site = g & (NS - 1);
    int u = g >> 14;  // whole block shares one u

    for (int s = threadIdx.x; s < 297; s += 128) {
        int v = s / 33, w = s % 33;
        wt[w * 9 + v] = weight[u * 297 + s];
    }
    __syncthreads();

    // copy gauge link channel u to output
    {
        const float2* src = (const float2*)(x + site * 144 + u * 18);
        float2* dst = (float2*)(out + site * 144 + u * 18);
#pragma unroll
        for (int m = 0; m < 9; m++) dst[m] = src[m];
    }

    float accr[3][3], acci[3][3];
#pragma unroll
    for (int i = 0; i < 3; i++)
#pragma unroll
        for (int j = 0; j < 3; j++) { accr[i][j] = 0.f; acci[i][j] = 0.f; }

    // 3 passes over v-groups
#pragma unroll
    for (int vb = 0; vb < 9; vb += 3) {
        float Mr[3][9], Mi[3][9];
#pragma unroll
        for (int t = 0; t < 3; t++)
#pragma unroll
            for (int m = 0; m < 9; m++) { Mr[t][m] = 0.f; Mi[t][m] = 0.f; }

        // ring-of-3 prefetch buffers
        float4 Tb4[3][4];
        float2 Tb2[3];
#pragma unroll
        for (int q = 0; q < 4; q++) Tb4[0][q] = g_T4[q * NS + site];
        Tb2[0] = g_T2[site];
#pragma unroll
        for (int q = 0; q < 4; q++) Tb4[1][q] = g_T4[(4 + q) * NS + site];
        Tb2[1] = g_T2[NS + site];

#pragma unroll
        for (int k = 0; k < 16; k++) {
            const int cur = k % 3;
            if (k < 14) {
                const int nxt = (k + 2) % 3;
#pragma unroll
                for (int q = 0; q < 4; q++)
                    Tb4[nxt][q] = g_T4[((k + 2) * 4 + q) * NS + site];
                Tb2[nxt] = g_T2[(k + 2) * NS + site];
            }
            // unpack T
            float Tr[9], Ti[9];
#pragma unroll
            for (int q = 0; q < 4; q++) {
                Tr[2 * q]     = Tb4[cur][q].x;
                Ti[2 * q]     = Tb4[cur][q].y;
                Tr[2 * q + 1] = Tb4[cur][q].z;
                Ti[2 * q + 1] = Tb4[cur][q].w;
            }
            Tr[8] = Tb2[cur].x;
            Ti[8] = Tb2[cur].y;

#pragma unroll
            for (int t = 0; t < 3; t++) {
                const int v = vb + t;
                float c1 = wt[k * 9 + v];
                float c2 = wt[(16 + k) * 9 + v];
#pragma unroll
                for (int i = 0; i < 3; i++)
#pragma unroll
                    for (int j = 0; j < 3; j++) {
                        Mr[t][i * 3 + j] += c1 * Tr[i * 3 + j] + c2 * Tr[j * 3 + i];
                        Mi[t][i * 3 + j] += c1 * Ti[i * 3 + j] - c2 * Ti[j * 3 + i];
                    }
            }
        }

        // epilogue: N = M + c3 I ; acc += A_v @ N
#pragma unroll
        for (int t = 0; t < 3; t++) {
            const int v = vb + t;
            float c3 = wt[288 + v];
            float nr[3][3], ni[3][3];
#pragma unroll
            for (int i = 0; i < 3; i++)
#pragma unroll
                for (int j = 0; j < 3; j++) {
                    nr[i][j] = Mr[t][i * 3 + j] + ((i == j) ? c3 : 0.f);
                    ni[i][j] = Mi[t][i * 3 + j];
                }

            if (v == 8) {
#pragma unroll
                for (int i = 0; i < 3; i++)
#pragma unroll
                    for (int j = 0; j < 3; j++) { accr[i][j] += nr[i][j]; acci[i][j] += ni[i][j]; }
            } else {
                const int c = (v < 4) ? v : (v - 4);
                float wr[3][3], wi[3][3];
#pragma unroll
                for (int q = 0; q < 4; q++) {
                    float4 t4 = g_T4[((16 + c) * 4 + q) * NS + site];
                    wr[(2 * q) / 3][(2 * q) % 3] = t4.x;
                    wi[(2 * q) / 3][(2 * q) % 3] = t4.y;
                    wr[(2 * q + 1) / 3][(2 * q + 1) % 3] = t4.z;
                    wi[(2 * q + 1) / 3][(2 * q + 1) % 3] = t4.w;
                }
                {
                    float2 t2 = g_T2[(16 + c) * NS + site];
                    wr[2][2] = t2.x;
                    wi[2][2] = t2.y;
                }
                if (v < 4) {
                    // acc += w_c @ N
#pragma unroll
                    for (int i = 0; i < 3; i++)
#pragma unroll
                        for (int kk = 0; kk < 3; kk++) {
                            float cr = accr[i][kk], ci = acci[i][kk];
#pragma unroll
                            for (int j = 0; j < 3; j++) {
                                cr += wr[i][j] * nr[j][kk] - wi[i][j] * ni[j][kk];
                                ci += wr[i][j] * ni[j][kk] + wi[i][j] * nr[j][kk];
                            }
                            accr[i][kk] = cr; acci[i][kk] = ci;
                        }
                } else {
                    // acc += w_c^dag @ N : conj(w[j][i]) * N[j][kk]
#pragma unroll
                    for (int i = 0; i < 3; i++)
#pragma unroll
                        for (int kk = 0; kk < 3; kk++) {
                            float cr = accr[i][kk], ci = acci[i][kk];
#pragma unroll
                            for (int j = 0; j < 3; j++) {
                                cr += wr[j][i] * nr[j][kk] + wi[j][i] * ni[j][kk];
                                ci += wr[j][i] * ni[j][kk] - wi[j][i] * nr[j][kk];
                            }
                            accr[i][kk] = cr; acci[i][kk] = ci;
                        }
                }
            }
        }
    }

    float2* dst = (float2*)(out + site * 144 + (4 + u) * 18);
#pragma unroll
    for (int i = 0; i < 3; i++)
#pragma unroll
        for (int j = 0; j < 3; j++)
            dst[i * 3 + j] = make_float2(accr[i][j], acci[i][j]);
}

extern "C" void kernel_launch(void* const* d_in, const int* in_sizes, int n_in,
                              void* d_out, int out_size) {
    const float* x = (const float*)d_in[0];
    const float* weight = (const float*)d_in[1];
    float* out = (float*)d_out;

    transport_kernel<<<4 * NS / 256, 256>>>(x);
    contract_kernel<<<4 * NS / 128, 128>>>(x, weight, out);
}

// round 10
// speedup vs baseline: 3.8107x; 3.8107x over previous
#include <cuda_runtime.h>

// GCMConv: gauge-covariant convolution on 8x8x16x16 lattice.
// x: (1, 16384, 8, 3, 3, 2) float32  [channels: 4 gauge links U_a, 4 fields w_c]
// weight: (4, 9, 33) float32
// out: (1, 16384, 8, 3, 3, 2): [U (copied), w_out]
//
// M-form, scalar FFMA, 3-pass v-split, R2-style loop discipline:
//   M_v = sum_k c1_{vk} T_k + c2_{vk} T_k^dag   (+ c3_v I at epilogue)
//   w_out[u] = M_8 + sum_c w_c @ M_c + w_c^dag @ M_{4+c}
// Ring-2 double buffer (k&1) + #pragma unroll 2: bounds ptxas load hoisting
// so the ~140-float live set stays under the (128,3) 168-reg cap (no spills).

#define NS 16384

// Scratch layout (element-pair-major for float4 loads):
//  g_T4[(r*4 + q)*NS + site] : elements 2q, 2q+1 of matrix r as (re,im,re,im)
//  g_T2[r*NS + site]         : element 8 of matrix r as (re,im)
//  r = 0..15 : T_k ; r = 16+c : own-site w_c
__device__ float4 g_T4[80 * NS];
__device__ float2 g_T2[20 * NS];

__global__ __launch_bounds__(256) void transport_kernel(const float* __restrict__ x) {
    int g = blockIdx.x * 256 + threadIdx.x;   // 0 .. 4*NS-1
    int site = g & (NS - 1);
    int a = g >> 14;                           // axis 0..3

    // periodic +1 neighbor; dims (8,8,16,16), strides (2048,256,16,1)
    int d3 = site & 15, d2 = (site >> 4) & 15, d1 = (site >> 8) & 7, d0 = (site >> 11) & 7;
    int nbr;
    if (a == 0)      nbr = site + ((((d0 + 1) & 7) - d0) << 11);
    else if (a == 1) nbr = site + ((((d1 + 1) & 7) - d1) << 8);
    else if (a == 2) nbr = site + ((((d2 + 1) & 15) - d2) << 4);
    else             nbr = site + (((d3 + 1) & 15) - d3);

    float Ur[3][3], Ui[3][3];
    {
        const float2* up = (const float2*)(x + site * 144 + a * 18);
#pragma unroll
        for (int m = 0; m < 9; m++) {
            float2 t = up[m];
            Ur[m / 3][m % 3] = t.x;
            Ui[m / 3][m % 3] = t.y;
        }
    }

#pragma unroll
    for (int c = 0; c < 4; c++) {
        float Wr[3][3], Wi[3][3];
        const float2* wp = (const float2*)(x + nbr * 144 + (4 + c) * 18);
#pragma unroll
        for (int m = 0; m < 9; m++) {
            float2 t = wp[m];
            Wr[m / 3][m % 3] = t.x;
            Wi[m / 3][m % 3] = t.y;
        }
        // t1 = U @ W
        float t1r[3][3], t1i[3][3];
#pragma unroll
        for (int i = 0; i < 3; i++)
#pragma unroll
            for (int kk = 0; kk < 3; kk++) {
                float cr = 0.f, ci = 0.f;
#pragma unroll
                for (int j = 0; j < 3; j++) {
                    cr += Ur[i][j] * Wr[j][kk] - Ui[i][j] * Wi[j][kk];
                    ci += Ur[i][j] * Wi[j][kk] + Ui[i][j] * Wr[j][kk];
                }
                t1r[i][kk] = cr;
                t1i[i][kk] = ci;
            }
        // T = t1 @ U^dag
        float Tr[9], Tiv[9];
#pragma unroll
        for (int i = 0; i < 3; i++)
#pragma unroll
            for (int kk = 0; kk < 3; kk++) {
                float cr = 0.f, ci = 0.f;
#pragma unroll
                for (int j = 0; j < 3; j++) {
                    float br = Ur[kk][j], bi = -Ui[kk][j];
                    cr += t1r[i][j] * br - t1i[i][j] * bi;
                    ci += t1r[i][j] * bi + t1i[i][j] * br;
                }
                Tr[i * 3 + kk] = cr;
                Tiv[i * 3 + kk] = ci;
            }
        int r = a * 4 + c;
#pragma unroll
        for (int q = 0; q < 4; q++)
            g_T4[(r * 4 + q) * NS + site] =
                make_float4(Tr[2 * q], Tiv[2 * q], Tr[2 * q + 1], Tiv[2 * q + 1]);
        g_T2[r * NS + site] = make_float2(Tr[8], Tiv[8]);
    }

    // own-site field: thread (site, a) handles channel c = a
    {
        const float2* wp = (const float2*)(x + site * 144 + (4 + a) * 18);
        float2 e[9];
#pragma unroll
        for (int m = 0; m < 9; m++) e[m] = wp[m];
        int r = 16 + a;
#pragma unroll
        for (int q = 0; q < 4; q++)
            g_T4[(r * 4 + q) * NS + site] =
                make_float4(e[2 * q].x, e[2 * q].y, e[2 * q + 1].x, e[2 * q + 1].y);
        g_T2[r * NS + site] = e[8];
    }
}

__global__ __launch_bounds__(128, 3) void contract_kernel(const float* __restrict__ x,
                                                          const float* __restrict__ weight,
                                                          float* __restrict__ out) {
    __shared__ float wt[297];   // [w*9 + v] = weight[u, v, w]

    int g = blockIdx.x * 128 + threadIdx.x;
    int site = g & (NS - 1);
    int u = g >> 14;  // whole block shares one u

    for (int s = threadIdx.x; s < 297; s += 128) {
        int v = s / 33, w = s % 33;
        wt[w * 9 + v] = weight[u * 297 + s];
    }
    __syncthreads();

    // copy gauge link channel u to output
    {
        const float2* src = (const float2*)(x + site * 144 + u * 18);
        float2* dst = (float2*)(out + site * 144 + u * 18);
#pragma unroll
        for (int m = 0; m < 9; m++) dst[m] = src[m];
    }

    float accr[3][3], acci[3][3];
#pragma unroll
    for (int i = 0; i < 3; i++)
#pragma unroll
        for (int j = 0; j < 3; j++) { accr[i][j] = 0.f; acci[i][j] = 0.f; }

    // 3 passes over v-groups {0,1,2}, {3,4,5}, {6,7,8}
#pragma unroll
    for (int vb = 0; vb < 9; vb += 3) {
        float Mr[3][9], Mi[3][9];
#pragma unroll
        for (int t = 0; t < 3; t++)
#pragma unroll
            for (int m = 0; m < 9; m++) { Mr[t][m] = 0.f; Mi[t][m] = 0.f; }

        // ring-2 double buffer, R2-style
        float4 Tb4[2][4];
        float2 Tb2[2];
#pragma unroll
        for (int q = 0; q < 4; q++) Tb4[0][q] = g_T4[q * NS + site];
        Tb2[0] = g_T2[site];

#pragma unroll 2
        for (int k = 0; k < 16; k++) {
            const int cur = k & 1;
            if (k < 15) {
#pragma unroll
                for (int q = 0; q < 4; q++)
                    Tb4[cur ^ 1][q] = g_T4[((k + 1) * 4 + q) * NS + site];
                Tb2[cur ^ 1] = g_T2[(k + 1) * NS + site];
            }
            // unpack T
            float Tr[9], Ti[9];
#pragma unroll
            for (int q = 0; q < 4; q++) {
                Tr[2 * q]     = Tb4[cur][q].x;
                Ti[2 * q]     = Tb4[cur][q].y;
                Tr[2 * q + 1] = Tb4[cur][q].z;
                Ti[2 * q + 1] = Tb4[cur][q].w;
            }
            Tr[8] = Tb2[cur].x;
            Ti[8] = Tb2[cur].y;

#pragma unroll
            for (int t = 0; t < 3; t++) {
                const int v = vb + t;
                float c1 = wt[k * 9 + v];
                float c2 = wt[(16 + k) * 9 + v];
#pragma unroll
                for (int i = 0; i < 3; i++)
#pragma unroll
                    for (int j = 0; j < 3; j++) {
                        Mr[t][i * 3 + j] += c1 * Tr[i * 3 + j] + c2 * Tr[j * 3 + i];
                        Mi[t][i * 3 + j] += c1 * Ti[i * 3 + j] - c2 * Ti[j * 3 + i];
                    }
            }
        }

        // epilogue: N = M + c3 I ; acc += A_v @ N
#pragma unroll
        for (int t = 0; t < 3; t++) {
            const int v = vb + t;
            float c3 = wt[288 + v];
            float nr[3][3], ni[3][3];
#pragma unroll
            for (int i = 0; i < 3; i++)
#pragma unroll
                for (int j = 0; j < 3; j++) {
                    nr[i][j] = Mr[t][i * 3 + j] + ((i == j) ? c3 : 0.f);
                    ni[i][j] = Mi[t][i * 3 + j];
                }

            if (v == 8) {
#pragma unroll
                for (int i = 0; i < 3; i++)
#pragma unroll
                    for (int j = 0; j < 3; j++) { accr[i][j] += nr[i][j]; acci[i][j] += ni[i][j]; }
            } else {
                const int c = (v < 4) ? v : (v - 4);
                float wr[3][3], wi[3][3];
#pragma unroll
                for (int q = 0; q < 4; q++) {
                    float4 t4 = g_T4[((16 + c) * 4 + q) * NS + site];
                    wr[(2 * q) / 3][(2 * q) % 3] = t4.x;
                    wi[(2 * q) / 3][(2 * q) % 3] = t4.y;
                    wr[(2 * q + 1) / 3][(2 * q + 1) % 3] = t4.z;
                    wi[(2 * q + 1) / 3][(2 * q + 1) % 3] = t4.w;
                }
                {
                    float2 t2 = g_T2[(16 + c) * NS + site];
                    wr[2][2] = t2.x;
                    wi[2][2] = t2.y;
                }
                if (v < 4) {
                    // acc += w_c @ N
#pragma unroll
                    for (int i = 0; i < 3; i++)
#pragma unroll
                        for (int kk = 0; kk < 3; kk++) {
                            float cr = accr[i][kk], ci = acci[i][kk];
#pragma unroll
                            for (int j = 0; j < 3; j++) {
                                cr += wr[i][j] * nr[j][kk] - wi[i][j] * ni[j][kk];
                                ci += wr[i][j] * ni[j][kk] + wi[i][j] * nr[j][kk];
                            }
                            accr[i][kk] = cr; acci[i][kk] = ci;
                        }
                } else {
                    // acc += w_c^dag @ N : conj(w[j][i]) * N[j][kk]
#pragma unroll
                    for (int i = 0; i < 3; i++)
#pragma unroll
                        for (int kk = 0; kk < 3; kk++) {
                            float cr = accr[i][kk], ci = acci[i][kk];
#pragma unroll
                            for (int j = 0; j < 3; j++) {
                                cr += wr[j][i] * nr[j][kk] + wi[j][i] * ni[j][kk];
                                ci += wr[j][i] * ni[j][kk] - wi[j][i] * nr[j][kk];
                            }
                            accr[i][kk] = cr; acci[i][kk] = ci;
                        }
                }
            }
        }
    }

    float2* dst = (float2*)(out + site * 144 + (4 + u) * 18);
#pragma unroll
    for (int i = 0; i < 3; i++)
#pragma unroll
        for (int j = 0; j < 3; j++)
            dst[i * 3 + j] = make_float2(accr[i][j], acci[i][j]);
}

extern "C" void kernel_launch(void* const* d_in, const int* in_sizes, int n_in,
                              void* d_out, int out_size) {
    const float* x = (const float*)d_in[0];
    const float* weight = (const float*)d_in[1];
    float* out = (float*)d_out;

    transport_kernel<<<4 * NS / 256, 256>>>(x);
    contract_kernel<<<4 * NS / 128, 128>>>(x, weight, out);
}